// round 17
// baseline (speedup 1.0000x reference)
#include <cuda_runtime.h>
#include <cuda_bf16.h>
#include <cstdint>

#define N_NODES 50000
#define N_EDGES 800000
#define IN_DIM  256
#define HIDDEN  128
#define OUT_DIM 64
#define NEG_SLOPE 0.1f

// Scratch (device globals: allocation-free rule)
__device__ __align__(16) float    g_h0[N_NODES * HIDDEN];   // encoder output (fp32)
__device__ __align__(16) unsigned g_h1a[N_NODES * 64];      // prescaled feats L0, bf16x2
__device__ __align__(16) unsigned g_h1c[N_NODES * 64];      // prescaled feats L1, bf16x2
__device__ float g_dinv[N_NODES];
__device__ int   g_cnt[N_NODES];
__device__ int   g_fill[N_NODES];      // seeded with rowptr by k_rowptr
__device__ int   g_rowptr[N_NODES + 1];
__device__ int   g_srcidx[N_EDGES];
__device__ int   g_blksum[256];
__device__ int   g_blkoff[256];
__device__ int   g_is64;

#define BUF_EXT 0
#define BUF_H0  1
#define SCAN_BLOCKS 196    // ceil(50000/256)
#define GEMM_BLOCKS 782    // ceil(50000/64)
#define EDGE_XBLK   256    // extra blocks fused onto GEMM launches

// ---------------------------------------------------------------------------
// Init + dtype detection
// ---------------------------------------------------------------------------
__global__ void k_init() {
    int i = blockIdx.x * blockDim.x + threadIdx.x;
    if (i < N_NODES) g_cnt[i] = 0;
    if (i == 0) g_is64 = 1;
}
// int64 edge_index with values < 50000 => every odd 32-bit word is zero.
__global__ void k_detect(const unsigned* __restrict__ e) {
    int i = blockIdx.x * blockDim.x + threadIdx.x;
    if (i < 4096) { if (e[2 * i + 1] != 0u) g_is64 = 0; }
}

// ---------------------------------------------------------------------------
// CSR scan: blocksum(+dinv) -> scan of block sums -> per-block scan(+fill seed)
// ---------------------------------------------------------------------------
__global__ __launch_bounds__(256) void k_blocksum() {
    __shared__ int s[256];
    int t = threadIdx.x;
    int i = blockIdx.x * 256 + t;
    int c = (i < N_NODES) ? g_cnt[i] : 0;
    if (i < N_NODES) g_dinv[i] = rsqrtf((float)c + 1.0f);   // +1 self loop
    s[t] = c; __syncthreads();
#pragma unroll
    for (int off = 128; off > 0; off >>= 1) {
        if (t < off) s[t] += s[t + off];
        __syncthreads();
    }
    if (t == 0) g_blksum[blockIdx.x] = s[0];
}

__global__ __launch_bounds__(256) void k_scanblk() {
    __shared__ int s[256];
    int t = threadIdx.x;
    int v = (t < SCAN_BLOCKS) ? g_blksum[t] : 0;
    s[t] = v; __syncthreads();
#pragma unroll
    for (int off = 1; off < 256; off <<= 1) {
        int u = (t >= off) ? s[t - off] : 0;
        __syncthreads(); s[t] += u; __syncthreads();
    }
    if (t < SCAN_BLOCKS) g_blkoff[t] = s[t] - v;            // exclusive
    if (t == 255) g_rowptr[N_NODES] = s[255];               // total
}

__global__ __launch_bounds__(256) void k_rowptr() {
    __shared__ int s[256];
    int t = threadIdx.x;
    int i = blockIdx.x * 256 + t;
    int c = (i < N_NODES) ? g_cnt[i] : 0;
    s[t] = c; __syncthreads();
#pragma unroll
    for (int off = 1; off < 256; off <<= 1) {
        int u = (t >= off) ? s[t - off] : 0;
        __syncthreads(); s[t] += u; __syncthreads();
    }
    if (i < N_NODES) {
        int rp = g_blkoff[blockIdx.x] + s[t] - c;           // exclusive
        g_rowptr[i] = rp;
        g_fill[i]   = rp;                                   // seed write cursor
    }
}

// ---------------------------------------------------------------------------
// Tiled fp32 GEMM with fused edge work in extra blocks (R14 winner, unchanged):
//   blocks [0, GEMM_BLOCKS)            : GEMM (TM=64, TK=64, k-unroll x4)
//   blocks [GEMM_BLOCKS, +EDGE_XBLK)   : PAR==1 hist | PAR==2 place
// MODE 0: +bias, leaky  (encoder: A=ext, out=g_h0)
// MODE 3: *dinv[m] -> bf16 pairs into g_h1a (transform0, prescaled)
// ---------------------------------------------------------------------------
template <int K, int C, int MODE, int SRC, int PAR>
__global__ __launch_bounds__(256)
void k_gemm(const float* __restrict__ Aext, const float* __restrict__ W,
            const float* __restrict__ bias, float* __restrict__ Oext,
            const void* __restrict__ ei)
{
    constexpr int TM = 64, TK = 64;
    constexpr int CG = C / 4;
    constexpr int RG = 256 / CG;
    constexpr int RPT = TM / RG;

    __shared__ float xs[TM][TK];
    __shared__ float ws[TK][C];

    if (PAR != 0 && blockIdx.x >= GEMM_BLOCKS) {
        const int t0 = (blockIdx.x - GEMM_BLOCKS) * 256 + threadIdx.x;
        const int stride = EDGE_XBLK * 256;
        const int is64 = g_is64;
        if (PAR == 1) {            // histogram of dst
            for (int e = t0; e < N_EDGES; e += stride) {
                int d = is64 ? (int)((const long long*)ei)[N_EDGES + e]
                             : ((const int*)ei)[N_EDGES + e];
                atomicAdd(&g_cnt[d], 1);
            }
        } else {                   // CSR placement (g_fill pre-seeded w/ rowptr)
            for (int e = t0; e < N_EDGES; e += stride) {
                int s, d;
                if (is64) {
                    s = (int)((const long long*)ei)[e];
                    d = (int)((const long long*)ei)[N_EDGES + e];
                } else {
                    s = ((const int*)ei)[e];
                    d = ((const int*)ei)[N_EDGES + e];
                }
                g_srcidx[atomicAdd(&g_fill[d], 1)] = s;
            }
        }
        return;
    }

    const float* A   = (SRC == BUF_H0) ? g_h0 : Aext;
    float*       out = (MODE == 0) ? g_h0 : Oext;

    const int m0  = blockIdx.x * TM;
    const int tid = threadIdx.x;
    const int cg  = tid % CG;
    const int rg  = tid / CG;

    float acc[RPT][4];
#pragma unroll
    for (int r = 0; r < RPT; r++)
#pragma unroll
        for (int j = 0; j < 4; j++) acc[r][j] = 0.0f;

    for (int kt = 0; kt < K; kt += TK) {
#pragma unroll
        for (int i = tid; i < TM * TK / 4; i += 256) {
            int row = (i * 4) / TK, col = (i * 4) % TK;
            int m = m0 + row;
            float4 v = make_float4(0.f, 0.f, 0.f, 0.f);
            if (m < N_NODES)
                v = *(const float4*)&A[(size_t)m * K + kt + col];
            *(float4*)&xs[row][col] = v;
        }
#pragma unroll
        for (int i = tid; i < TK * C / 4; i += 256) {
            int row = (i * 4) / C, col = (i * 4) % C;
            *(float4*)&ws[row][col] = *(const float4*)&W[(size_t)(kt + row) * C + col];
        }
        __syncthreads();

#pragma unroll
        for (int k = 0; k < TK; k += 4) {
            float4 wv0 = *(const float4*)&ws[k + 0][cg * 4];
            float4 wv1 = *(const float4*)&ws[k + 1][cg * 4];
            float4 wv2 = *(const float4*)&ws[k + 2][cg * 4];
            float4 wv3 = *(const float4*)&ws[k + 3][cg * 4];
#pragma unroll
            for (int r = 0; r < RPT; r++) {
                float4 a4 = *(const float4*)&xs[rg * RPT + r][k];
                acc[r][0] += a4.x * wv0.x; acc[r][1] += a4.x * wv0.y;
                acc[r][2] += a4.x * wv0.z; acc[r][3] += a4.x * wv0.w;
                acc[r][0] += a4.y * wv1.x; acc[r][1] += a4.y * wv1.y;
                acc[r][2] += a4.y * wv1.z; acc[r][3] += a4.y * wv1.w;
                acc[r][0] += a4.z * wv2.x; acc[r][1] += a4.z * wv2.y;
                acc[r][2] += a4.z * wv2.z; acc[r][3] += a4.z * wv2.w;
                acc[r][0] += a4.w * wv3.x; acc[r][1] += a4.w * wv3.y;
                acc[r][2] += a4.w * wv3.z; acc[r][3] += a4.w * wv3.w;
            }
        }
        __syncthreads();
    }

#pragma unroll
    for (int r = 0; r < RPT; r++) {
        int m = m0 + rg * RPT + r;
        if (m >= N_NODES) continue;
        int c = cg * 4;
        float4 v = make_float4(acc[r][0], acc[r][1], acc[r][2], acc[r][3]);
        if (MODE == 0 || MODE == 1) {
            v.x += bias[c]; v.y += bias[c + 1]; v.z += bias[c + 2]; v.w += bias[c + 3];
        }
        if (MODE == 0) {
            v.x = v.x > 0.f ? v.x : NEG_SLOPE * v.x;
            v.y = v.y > 0.f ? v.y : NEG_SLOPE * v.y;
            v.z = v.z > 0.f ? v.z : NEG_SLOPE * v.z;
            v.w = v.w > 0.f ? v.w : NEG_SLOPE * v.w;
        }
        if (MODE == 3) {
            float di = g_dinv[m];
            __nv_bfloat162 p0 = __floats2bfloat162_rn(v.x * di, v.y * di);
            __nv_bfloat162 p1 = __floats2bfloat162_rn(v.z * di, v.w * di);
            uint2 u;
            u.x = *(unsigned*)&p0;
            u.y = *(unsigned*)&p1;
            *(uint2*)&g_h1a[(size_t)m * 64 + cg * 2] = u;
        } else {
            *(float4*)&out[(size_t)m * C + c] = v;
        }
    }
}

// ---------------------------------------------------------------------------
// Fused gather + GEMM: block prologue gathers its own 64 A-rows from the
// bf16 message table (ping-pong source), then GEMMs them against W (K=128).
//   h_row[d] = leaky(dinv[d]*(h1'[d] + sum_{s in CSR(d)} h1'[s]) + gbias)
// MODE 3: out = bf16(dinv*(row @ W)) -> g_h1c   (conv layer 1)
// MODE 1: out = row @ W + obias       -> Oext    (decoder)
// SRCSEL 0: gather from g_h1a    SRCSEL 1: gather from g_h1c
// ---------------------------------------------------------------------------
template <int C, int MODE, int SRCSEL>
__global__ __launch_bounds__(256)
void k_fused(const float* __restrict__ W, const float* __restrict__ gbias,
             const float* __restrict__ obias, float* __restrict__ Oext)
{
    constexpr int K  = HIDDEN;         // 128
    constexpr int TM = 64, TK = 64;
    constexpr int CG = C / 4;
    constexpr int RG = 256 / CG;
    constexpr int RPT = TM / RG;

    __shared__ float sa[TM][K];        // gathered A rows: 32 KB
    __shared__ float ws[TK][C];        // W chunk: 32 KB (C=128) | 16 KB

    const unsigned* hsrc = (SRCSEL == 0) ? g_h1a : g_h1c;

    const int tid  = threadIdx.x;
    const int wid  = tid >> 5;
    const int lane = tid & 31;
    const int m0   = blockIdx.x * TM;

    // ---- prologue: warp w gathers rows w*8 .. w*8+7 ----
#pragma unroll
    for (int i = 0; i < 8; i++) {
        int r = wid * 8 + i;
        int d = m0 + r;
        float4 acc = make_float4(0.f, 0.f, 0.f, 0.f);
        if (d < N_NODES) {
            float dd = g_dinv[d];
            uint2 su = *(const uint2*)&hsrc[(size_t)d * 64 + lane * 2];
            float2 f0 = __bfloat1622float2(*(__nv_bfloat162*)&su.x);
            float2 f1 = __bfloat1622float2(*(__nv_bfloat162*)&su.y);
            acc = make_float4(f0.x, f0.y, f1.x, f1.y);
            int beg = g_rowptr[d], end = g_rowptr[d + 1];
            for (int j0 = beg; j0 < end; j0 += 32) {
                int n = min(32, end - j0);
                int myidx = (j0 + lane < end) ? g_srcidx[j0 + lane] : 0;
                for (int c = 0; c < n; c++) {
                    int s = __shfl_sync(0xffffffffu, myidx, c);
                    uint2 u = *(const uint2*)&hsrc[(size_t)s * 64 + lane * 2];
                    float2 a = __bfloat1622float2(*(__nv_bfloat162*)&u.x);
                    float2 b = __bfloat1622float2(*(__nv_bfloat162*)&u.y);
                    acc.x += a.x; acc.y += a.y; acc.z += b.x; acc.w += b.y;
                }
            }
            int c0 = lane * 4;
            acc.x = acc.x * dd + gbias[c0];
            acc.y = acc.y * dd + gbias[c0 + 1];
            acc.z = acc.z * dd + gbias[c0 + 2];
            acc.w = acc.w * dd + gbias[c0 + 3];
            acc.x = acc.x > 0.f ? acc.x : NEG_SLOPE * acc.x;
            acc.y = acc.y > 0.f ? acc.y : NEG_SLOPE * acc.y;
            acc.z = acc.z > 0.f ? acc.z : NEG_SLOPE * acc.z;
            acc.w = acc.w > 0.f ? acc.w : NEG_SLOPE * acc.w;
        }
        *(float4*)&sa[r][lane * 4] = acc;
    }
    __syncthreads();

    // ---- GEMM: A resident in sa, stage W in TK chunks ----
    const int cg = tid % CG;
    const int rg = tid / CG;

    float acc[RPT][4];
#pragma unroll
    for (int r = 0; r < RPT; r++)
#pragma unroll
        for (int j = 0; j < 4; j++) acc[r][j] = 0.0f;

    for (int kt = 0; kt < K; kt += TK) {
#pragma unroll
        for (int i = tid; i < TK * C / 4; i += 256) {
            int row = (i * 4) / C, col = (i * 4) % C;
            *(float4*)&ws[row][col] = *(const float4*)&W[(size_t)(kt + row) * C + col];
        }
        __syncthreads();

#pragma unroll
        for (int k = 0; k < TK; k += 4) {
            float4 wv0 = *(const float4*)&ws[k + 0][cg * 4];
            float4 wv1 = *(const float4*)&ws[k + 1][cg * 4];
            float4 wv2 = *(const float4*)&ws[k + 2][cg * 4];
            float4 wv3 = *(const float4*)&ws[k + 3][cg * 4];
#pragma unroll
            for (int r = 0; r < RPT; r++) {
                float4 a4 = *(const float4*)&sa[rg * RPT + r][kt + k];
                acc[r][0] += a4.x * wv0.x; acc[r][1] += a4.x * wv0.y;
                acc[r][2] += a4.x * wv0.z; acc[r][3] += a4.x * wv0.w;
                acc[r][0] += a4.y * wv1.x; acc[r][1] += a4.y * wv1.y;
                acc[r][2] += a4.y * wv1.z; acc[r][3] += a4.y * wv1.w;
                acc[r][0] += a4.z * wv2.x; acc[r][1] += a4.z * wv2.y;
                acc[r][2] += a4.z * wv2.z; acc[r][3] += a4.z * wv2.w;
                acc[r][0] += a4.w * wv3.x; acc[r][1] += a4.w * wv3.y;
                acc[r][2] += a4.w * wv3.z; acc[r][3] += a4.w * wv3.w;
            }
        }
        __syncthreads();
    }

    // ---- epilogue ----
#pragma unroll
    for (int r = 0; r < RPT; r++) {
        int m = m0 + rg * RPT + r;
        if (m >= N_NODES) continue;
        int c = cg * 4;
        float4 v = make_float4(acc[r][0], acc[r][1], acc[r][2], acc[r][3]);
        if (MODE == 3) {
            float di = g_dinv[m];
            __nv_bfloat162 p0 = __floats2bfloat162_rn(v.x * di, v.y * di);
            __nv_bfloat162 p1 = __floats2bfloat162_rn(v.z * di, v.w * di);
            uint2 u;
            u.x = *(unsigned*)&p0;
            u.y = *(unsigned*)&p1;
            *(uint2*)&g_h1c[(size_t)m * 64 + cg * 2] = u;
        } else {
            v.x += obias[c]; v.y += obias[c + 1];
            v.z += obias[c + 2]; v.w += obias[c + 3];
            *(float4*)&Oext[(size_t)m * C + c] = v;
        }
    }
}

// ---------------------------------------------------------------------------
// Launch
// ---------------------------------------------------------------------------
extern "C" void kernel_launch(void* const* d_in, const int* in_sizes, int n_in,
                              void* d_out, int out_size)
{
    const float* x      = (const float*)d_in[0];
    const void*  ei     = d_in[1];                 // int32 or int64, detected
    const float* enc_W  = (const float*)d_in[2];
    const float* enc_b  = (const float*)d_in[3];
    const float* conv_W = (const float*)d_in[4];   // [2,128,128]
    const float* conv_b = (const float*)d_in[5];   // [2,128]
    const float* dec_W  = (const float*)d_in[6];
    const float* dec_b  = (const float*)d_in[7];
    float*       out    = (float*)d_out;

    const int nodeBlocks = (N_NODES + 255) / 256;       // 196

    k_init<<<nodeBlocks, 256>>>();
    k_detect<<<16, 256>>>((const unsigned*)ei);

    // encoder GEMM  ∪  dst-histogram (fused, independent)
    k_gemm<IN_DIM, HIDDEN, 0, BUF_EXT, 1>
        <<<GEMM_BLOCKS + EDGE_XBLK, 256>>>(x, enc_W, enc_b, nullptr, ei);

    k_blocksum<<<SCAN_BLOCKS, 256>>>();
    k_scanblk<<<1, 256>>>();
    k_rowptr<<<SCAN_BLOCKS, 256>>>();                   // also seeds g_fill

    // transform0 GEMM (h0 -> h1a bf16 prescaled)  ∪  CSR placement
    k_gemm<HIDDEN, HIDDEN, 3, BUF_H0, 2>
        <<<GEMM_BLOCKS + EDGE_XBLK, 256>>>(nullptr, conv_W, nullptr, nullptr, ei);

    // fused: gather(h1a)+leaky  ->  @conv_W[1] -> h1c (bf16 prescaled)
    k_fused<HIDDEN, 3, 0><<<GEMM_BLOCKS, 256>>>(
        conv_W + (size_t)HIDDEN * HIDDEN, conv_b, nullptr, nullptr);

    // fused: gather(h1c)+leaky  ->  @dec_W + dec_b -> out
    k_fused<OUT_DIM, 1, 1><<<GEMM_BLOCKS, 256>>>(
        dec_W, conv_b + HIDDEN, dec_b, out);
}